// round 13
// baseline (speedup 1.0000x reference)
#include <cuda_runtime.h>
#include <cuda_bf16.h>
#include <math.h>

// ---------------------------------------------------------------------------
// BoxListHNMS — exact via rank-closed candidate pruning. 3-kernel pipeline:
//   K1: block0 samples scores -> threshold T; other blocks clear tables
//   K2: scan scores, compact (score,idx) of candidates (tiny body)
//   K3: dense insert (1 thr/candidate) -> release/acquire ticket -> last
//       block: resolve + bucket-rank select + output (all in shared)
// Rank-closure: only better-ranked boxes eliminate, so keep-status inside
// {score >= T} is exact; top-maxp keepers are exact while keepers >= maxp.
// ---------------------------------------------------------------------------

typedef unsigned long long u64;
typedef unsigned int u32;
typedef unsigned short u16;

#define RTARGET 4096
#define CMAX    8192
#define TBITS   15
#define TSIZE   (1 << TBITS)       // 32768 slots/table, 2MB total
#define TMASK   (TSIZE - 1)
#define EMPTYK  0xFFFFFFFFFFFFFFFFull
#define NBIN    8192               // sample-histogram bins over [0,1]
#define FBIN    4096               // keeper bins over [T,1]
#define SELCAP  2048
#define FULLM   0xFFFFFFFFu

__device__ u64  g_tabk[4][TSIZE];
__device__ u64  g_tabv[4][TSIZE];
__device__ u64  g_cval[CMAX];
__device__ u32  g_cslot[4][CMAX];
__device__ float g_pow[128];
__device__ float g_log_a;
__device__ u32  g_ccnt;
__device__ u32  g_thresh;          // float bits of threshold T
__device__ u32  g_tick;
__device__ int  g_num;

__device__ __forceinline__ u64 mix64(u64 x) {
    x += 0x9E3779B97F4A7C15ull;
    x = (x ^ (x >> 30)) * 0xBF58476D1CE4E5B9ull;
    x = (x ^ (x >> 27)) * 0x94D049BB133111EBull;
    return x ^ (x >> 31);
}

// release our block's prior writes / acquire all earlier blocks' writes
__device__ __forceinline__ u32 ticket_acq_rel(u32* p) {
    u32 old;
    asm volatile("atom.add.acq_rel.gpu.global.u32 %0, [%1], 1;"
                 : "=r"(old) : "l"(p) : "memory");
    return old;
}

// ---------------------------------------------------------------------------
// K1: block 0 = scalars + CR pow + sampled threshold; blocks 1.. clear tables
// ---------------------------------------------------------------------------
__global__ __launch_bounds__(1024) void init_sample_k(const float* __restrict__ scores,
                                                      const int* num_ptr, int N) {
    if (blockIdx.x == 0) {
        __shared__ u32 sh_hist[NBIN];      // 32KB
        __shared__ u32 sh_scan[1024];
        int t = threadIdx.x;
        if (t == 0) {
            int num = num_ptr ? *num_ptr : 4;
            if (num < 1) num = 1;
            if (num > 4) num = 4;
            g_num = num;
            g_ccnt = 0; g_thresh = 0; g_tick = 0;
            g_log_a = (float)log((double)0.71f);                      // CR f32
        }
        if (t < 128)
            g_pow[t] = (float)pow((double)0.71f, (double)(t - 64));   // CR f32
        for (int i = t; i < NBIN; i += 1024) sh_hist[i] = 0u;
        __syncthreads();

        long S;
        if (N >= 65536) {
            S = 65536;
            // 16384 float4 loads spread over N; per thread 16 loads, MLP 4
            long f4s = ((long)N / 4) / 16384; if (f4s < 1) f4s = 1;
            const float4* s4 = (const float4*)scores;
            for (int kk = 0; kk < 16; kk += 4) {
                float4 v[4];
                #pragma unroll
                for (int u = 0; u < 4; u++) {
                    long j = (long)(kk + u) * 1024 + t;
                    v[u] = s4[j * f4s];
                }
                #pragma unroll
                for (int u = 0; u < 4; u++) {
                    float f[4] = {v[u].x, v[u].y, v[u].z, v[u].w};
                    #pragma unroll
                    for (int e = 0; e < 4; e++) {
                        int b = (int)(f[e] * (float)NBIN);
                        if (b < 0) b = 0;
                        if (b > NBIN - 1) b = NBIN - 1;
                        atomicAdd(&sh_hist[b], 1u);
                    }
                }
            }
        } else {
            S = N;
            for (int i = t; i < N; i += 1024) {
                int b = (int)(scores[i] * (float)NBIN);
                if (b < 0) b = 0;
                if (b > NBIN - 1) b = NBIN - 1;
                atomicAdd(&sh_hist[b], 1u);
            }
        }
        __syncthreads();

        u32 tgt = (u32)(((u64)RTARGET * (u64)S) / (u64)(N > 0 ? N : 1));
        if (tgt < 1) tgt = 1;

        u32 b0 = (u32)t * 8u;
        u32 local = 0;
        #pragma unroll
        for (int j = 0; j < 8; j++) local += sh_hist[b0 + j];
        sh_scan[t] = local;
        __syncthreads();
        for (int d = 1; d < 1024; d <<= 1) {
            u32 v = (t + d < 1024) ? sh_scan[t + d] : 0u;
            __syncthreads();
            sh_scan[t] += v;
            __syncthreads();
        }
        u32 cum = (t < 1023) ? sh_scan[t + 1] : 0u;
        for (int b = 7; b >= 0; b--) {
            u32 c = sh_hist[b0 + b];
            if (c && cum < tgt && cum + c >= tgt)
                g_thresh = __float_as_uint((float)(b0 + b) / (float)NBIN);
            cum += c;
        }
    } else {
        int gt = (blockIdx.x - 1) * blockDim.x + threadIdx.x;
        int gs = (gridDim.x - 1) * blockDim.x;
        for (int i = gt; i < 4 * TSIZE; i += gs) {
            ((u64*)g_tabk)[i] = EMPTYK;
            ((u64*)g_tabv)[i] = 0ull;
        }
    }
}

// ---------------------------------------------------------------------------
// K2: scan scores, write packed (score_bits, ~idx) for candidates only.
// ---------------------------------------------------------------------------
__global__ __launch_bounds__(256) void scan_k(const float* __restrict__ scores, int N) {
    int t = blockIdx.x * blockDim.x + threadIdx.x;
    int lane = threadIdx.x & 31;
    long base = (long)t * 8;
    u32 T = g_thresh;

    u32 sb[8];
    u32 pmask = 0;
    if (base + 8 <= N) {
        const float4* s4 = (const float4*)(scores + base);
        float4 a = s4[0], b = s4[1];
        sb[0] = __float_as_uint(a.x); sb[1] = __float_as_uint(a.y);
        sb[2] = __float_as_uint(a.z); sb[3] = __float_as_uint(a.w);
        sb[4] = __float_as_uint(b.x); sb[5] = __float_as_uint(b.y);
        sb[6] = __float_as_uint(b.z); sb[7] = __float_as_uint(b.w);
        #pragma unroll
        for (int j = 0; j < 8; j++) if (sb[j] >= T) pmask |= (1u << j);
    } else if (base < N) {
        #pragma unroll
        for (int j = 0; j < 8; j++) {
            if (base + j < N) {
                sb[j] = __float_as_uint(scores[base + j]);
                if (sb[j] >= T) pmask |= (1u << j);
            }
        }
    }
    u32 cnt = __popc(pmask);

    u32 inc = cnt;
    #pragma unroll
    for (int d = 1; d < 32; d <<= 1) {
        u32 v = __shfl_up_sync(FULLM, inc, d);
        if (lane >= d) inc += v;
    }
    u32 wtot = __shfl_sync(FULLM, inc, 31);
    u32 wbase = 0;
    if (lane == 31 && wtot) wbase = atomicAdd(&g_ccnt, wtot);
    wbase = __shfl_sync(FULLM, wbase, 31);
    u32 p = wbase + inc - cnt;

    while (pmask) {
        int j = __ffs(pmask) - 1;
        pmask &= pmask - 1;
        if (p < CMAX)
            g_cval[p] = ((u64)sb[j] << 32) | (u64)(0xFFFFFFFFu - (u32)(base + j));
        p++;
    }
}

// ---------------------------------------------------------------------------
// K3: dense insert (1 thread/candidate) -> ticket -> last block: resolve +
// bucket-rank select + output. 8 blocks x 1024 threads.
// ---------------------------------------------------------------------------
__global__ __launch_bounds__(1024) void insert_finale_k(const float4* __restrict__ rects,
                                                        int maxp, float* __restrict__ out) {
    __shared__ u32 s_suf[FBIN];            // 16KB: hist -> rank-base counters
    __shared__ u32 s_scan[1024];           // 4KB
    __shared__ u64 s_key[SELCAP];          // 16KB
    __shared__ u16 s_bin[SELCAP];          // 4KB
    __shared__ u32 s_keep[CMAX / 32];      // 1KB bitmask
    __shared__ u32 s_bsel, s_ksel;
    __shared__ bool isLast;

    int tid = threadIdx.x;
    u32 cc = g_ccnt; if (cc > CMAX) cc = CMAX;
    const int num = g_num;
    u32 T = g_thresh;
    float Tf = __uint_as_float(T);
    float inv = (Tf < 0.999999f) ? ((float)FBIN / (1.0f - Tf)) : 0.0f;

    // ---- phase 1: dense insert, one candidate per thread ----
    u32 i = blockIdx.x * blockDim.x + tid;
    if (i < cc) {
        u64 val = g_cval[i];
        u32 gi = 0xFFFFFFFFu - (u32)(val & 0xFFFFFFFFull);
        float4 r = rects[gi];
        const float cx = r.x, cy = r.y, w = r.z, h = r.w;
        const float log_a = g_log_a;
        const float STEPF = (float)(1.0 / 0.71 - 1.0);

        float rw = logf(w) / log_a, rh = logf(h) / log_a;
        bool risky = false;
        #pragma unroll
        for (int m = 0; m < 4; m++) {
            if (m >= num) break;
            float off = (float)((double)m / (double)num);
            float fw = rw + off, fh = rh + off;
            float aw = fw - floorf(fw), ah = fh - floorf(fh);
            risky |= (aw < 1e-5f) | (aw > 1.0f - 1e-5f) | (ah < 1e-5f) | (ah > 1.0f - 1e-5f);
        }
        if (risky) {
            rw = (float)log((double)w) / log_a;
            rh = (float)log((double)h) / log_a;
        }

        for (int m = 0; m < num; m++) {
            float off = (float)((double)m / (double)num);
            int qw = (int)floorf(rw + off);
            int qh = (int)floorf(rh + off);
            int iw = qw + 64; iw = iw < 0 ? 0 : (iw > 127 ? 127 : iw);
            int ih = qh + 64; ih = ih < 0 ? 0 : (ih > 127 ? 127 : ih);
            float denw = STEPF * g_pow[iw];
            float denh = STEPF * g_pow[ih];
            int qx = (int)floorf(cx / denw + off);
            int qy = (int)floorf(cy / denh + off);
            u32 kh = (u32)((qw + 64) * 128 + (qh + 64));
            u32 kl = (u32)qx * 65536u + (u32)qy;
            u64 key = ((u64)kh << 32) | (u64)kl;

            u32 slot = (u32)mix64(key) & TMASK;
            for (;;) {
                u64 k = g_tabk[m][slot];
                if (k == key) break;
                if (k == EMPTYK) {
                    u64 old = atomicCAS(&g_tabk[m][slot], EMPTYK, key);
                    if (old == EMPTYK || old == key) break;
                }
                slot = (slot + 1) & TMASK;
            }
            atomicMax(&g_tabv[m][slot], val);
            g_cslot[m][i] = slot;
        }
    }

    // ---- ticket: one acq_rel RMW per block ----
    __syncthreads();
    if (tid == 0)
        isLast = (ticket_acq_rel(&g_tick) == (u32)gridDim.x - 1u);
    __syncthreads();
    if (!isLast) return;

    // ---- phase 2 (last block only): resolve + keeper hist ----
    for (int j = tid; j < FBIN; j += 1024) s_suf[j] = 0u;
    for (int j = tid; j < CMAX / 32; j += 1024) s_keep[j] = 0u;
    if (tid == 0) { s_bsel = 0; s_ksel = 0; }
    __syncthreads();

    for (u32 k = tid; k < cc; k += 1024) {
        u64 val = __ldcg(&g_cval[k]);
        u32 sl[4];
        #pragma unroll
        for (int m = 0; m < 4; m++)
            sl[m] = (m < num) ? __ldcg(&g_cslot[m][k]) : 0u;
        u64 tv[4];
        #pragma unroll
        for (int m = 0; m < 4; m++)
            tv[m] = (m < num) ? __ldcg(&g_tabv[m][sl[m]]) : val;
        bool ok = (tv[0] == val) & (tv[1] == val) & (tv[2] == val) & (tv[3] == val);
        if (ok) {
            atomicOr(&s_keep[k >> 5], 1u << (k & 31));
            float sf = __uint_as_float((u32)(val >> 32));
            int rel = (int)((sf - Tf) * inv);
            if (rel < 0) rel = 0;
            if (rel > FBIN - 1) rel = FBIN - 1;
            atomicAdd(&s_suf[rel], 1u);
        }
    }
    __syncthreads();

    // ---- suffix-scan bins -> bsel + rank bases (in place) ----
    u32 b0 = (u32)tid * 4u;
    u32 c0 = s_suf[b0], c1 = s_suf[b0 + 1], c2 = s_suf[b0 + 2], c3 = s_suf[b0 + 3];
    s_scan[tid] = c0 + c1 + c2 + c3;
    __syncthreads();
    for (int d = 1; d < 1024; d <<= 1) {
        u32 v = (tid + d < 1024) ? s_scan[tid + d] : 0u;
        __syncthreads();
        s_scan[tid] += v;
        __syncthreads();
    }
    u32 cum = (tid < 1023) ? s_scan[tid + 1] : 0u;
    s_suf[b0 + 3] = cum;
    s_suf[b0 + 2] = cum + c3;
    s_suf[b0 + 1] = cum + c3 + c2;
    s_suf[b0 + 0] = cum + c3 + c2 + c1;
    {
        u32 cc2 = cum;
        u32 cs[4] = {c0, c1, c2, c3};
        for (int b = 3; b >= 0; b--) {
            u32 c = cs[b];
            if (c && cc2 < (u32)maxp && cc2 + c >= (u32)maxp) {
                s_bsel = b0 + (u32)b;
                s_ksel = cc2 + c;
            }
            cc2 += c;
        }
    }
    // if total keepers < maxp, select all
    if (tid == 0 && s_ksel == 0) s_ksel = s_scan[0];
    __syncthreads();
    u32 bsel = s_bsel;
    u32 ksel = s_ksel; if (ksel > (u32)SELCAP) ksel = (u32)SELCAP;

    // ---- claim bin-grouped slots for selected keepers ----
    for (u32 k = tid; k < cc; k += 1024) {
        if (!((s_keep[k >> 5] >> (k & 31)) & 1u)) continue;
        u64 v = __ldcg(&g_cval[k]);
        float sf = __uint_as_float((u32)(v >> 32));
        int rel = (int)((sf - Tf) * inv);
        if (rel < 0) rel = 0;
        if (rel > FBIN - 1) rel = FBIN - 1;
        if ((u32)rel >= bsel) {
            u32 slot = atomicAdd(&s_suf[rel], 1u);
            if (slot < (u32)SELCAP) {
                s_key[slot] = v;
                s_bin[slot] = (u16)rel;
            }
        }
    }
    __syncthreads();

    // ---- exact rank within tiny same-bin groups; write rows ----
    for (u32 s = tid; s < ksel; s += 1024) {
        u16 b = s_bin[s];
        u64 mykey = s_key[s];
        u32 g0 = s;
        while (g0 > 0 && s_bin[g0 - 1] == b) g0--;
        u32 g1 = s;
        while (g1 + 1 < ksel && s_bin[g1 + 1] == b) g1++;
        u32 rank = g0;
        for (u32 j = g0; j <= g1; j++) rank += (s_key[j] > mykey) ? 1u : 0u;
        if (rank < (u32)maxp) {
            u32 idx = 0xFFFFFFFFu - (u32)(mykey & 0xFFFFFFFFull);
            float4 bb = rects[idx];
            out[rank * 5 + 0] = bb.x;
            out[rank * 5 + 1] = bb.y;
            out[rank * 5 + 2] = bb.z;
            out[rank * 5 + 3] = bb.w;
            out[rank * 5 + 4] = __uint_as_float((u32)(mykey >> 32));
        }
    }
    u32 start = (ksel < (u32)maxp) ? ksel : (u32)maxp;
    for (u32 r = start + tid; r < (u32)maxp; r += 1024) {
        out[r * 5 + 0] = 0.f;
        out[r * 5 + 1] = 0.f;
        out[r * 5 + 2] = 0.f;
        out[r * 5 + 3] = 0.f;
        out[r * 5 + 4] = 0.f;
    }
}

// ---------------------------------------------------------------------------
extern "C" void kernel_launch(void* const* d_in, const int* in_sizes, int n_in,
                              void* d_out, int out_size) {
    const float* rects  = (const float*)d_in[0];
    const float* scores = (const float*)d_in[1];
    const int*   nump   = (n_in > 2) ? (const int*)d_in[2] : nullptr;
    int N = in_sizes[0] / 4;
    int maxp = out_size / 5;
    if (maxp > 1024) maxp = 1024;
    float* out = (float*)d_out;

    int nbs = (int)(((long)N + 2047) / 2048);   // K2: 8 elems/thread, 256 thr
    int nbf = CMAX / 1024;                      // K3: 1 thread/candidate

    init_sample_k  <<<64, 1024>>>(scores, nump, N);
    scan_k         <<<nbs, 256>>>(scores, N);
    insert_finale_k<<<nbf, 1024>>>((const float4*)rects, maxp, out);
}

// round 16
// speedup vs baseline: 1.6226x; 1.6226x over previous
#include <cuda_runtime.h>
#include <cuda_bf16.h>
#include <math.h>

// ---------------------------------------------------------------------------
// BoxListHNMS — exact via rank-closed candidate pruning. 4-kernel pipeline,
// every phase dense/parallel:
//   K1: block0 samples scores -> threshold T; other blocks clear tables+hist
//   K2: scan scores, compact (score,idx) of candidates (tiny body)
//   K3: keygen+insert (1 thr/candidate) -> co-resident spin barrier ->
//       resolve SAME candidates from registers -> keeper list + bin hist
//   K4: single block: suffix-scan bins, bucket-rank keepers, write output
// Rank-closure: only better-ranked boxes eliminate, so keep-status inside
// {score >= T} is exact; top-maxp keepers are exact while keepers >= maxp.
// ---------------------------------------------------------------------------

typedef unsigned long long u64;
typedef unsigned int u32;
typedef unsigned short u16;

#define RTARGET 4096
#define CMAX    8192
#define KMAX    4096
#define TBITS   15
#define TSIZE   (1 << TBITS)       // 32768 slots/table, 2MB total
#define TMASK   (TSIZE - 1)
#define EMPTYK  0xFFFFFFFFFFFFFFFFull
#define NBIN    8192               // sample-histogram bins over [0,1]
#define FBIN    4096               // keeper bins over [T,1]
#define SELCAP  2048
#define FULLM   0xFFFFFFFFu
#define IRBLK   32                 // K3 grid: co-resident for spin barrier

__device__ u64  g_tabk[4][TSIZE];
__device__ u64  g_tabv[4][TSIZE];
__device__ u64  g_cval[CMAX];
__device__ u64  g_kval[KMAX];
__device__ u32  g_hist2[FBIN];
__device__ float g_pow[128];
__device__ float g_log_a;
__device__ u32  g_ccnt;
__device__ u32  g_kcnt;
__device__ u32  g_thresh;          // float bits of threshold T
__device__ u32  g_tick;
__device__ int  g_num;

__device__ __forceinline__ u64 mix64(u64 x) {
    x += 0x9E3779B97F4A7C15ull;
    x = (x ^ (x >> 30)) * 0xBF58476D1CE4E5B9ull;
    x = (x ^ (x >> 27)) * 0x94D049BB133111EBull;
    return x ^ (x >> 31);
}

__device__ __forceinline__ u32 atom_add_acq_rel(u32* p) {
    u32 old;
    asm volatile("atom.add.acq_rel.gpu.global.u32 %0, [%1], 1;"
                 : "=r"(old) : "l"(p) : "memory");
    return old;
}
__device__ __forceinline__ u32 ld_acquire(u32* p) {
    u32 v;
    asm volatile("ld.acquire.gpu.global.u32 %0, [%1];"
                 : "=r"(v) : "l"(p) : "memory");
    return v;
}

// ---------------------------------------------------------------------------
// K1: block 0 = scalars + CR pow + sampled threshold (chunked loads, MLP 4);
//     blocks 1.. = clear hash tables + keeper hist.  (R10-proven)
// ---------------------------------------------------------------------------
__global__ __launch_bounds__(1024) void init_sample_k(const float* __restrict__ scores,
                                                      const int* num_ptr, int N) {
    if (blockIdx.x == 0) {
        __shared__ u32 sh_hist[NBIN];      // 32KB
        __shared__ u32 sh_scan[1024];
        int t = threadIdx.x;
        if (t == 0) {
            int num = num_ptr ? *num_ptr : 4;
            if (num < 1) num = 1;
            if (num > 4) num = 4;
            g_num = num;
            g_ccnt = 0; g_kcnt = 0; g_thresh = 0; g_tick = 0;
            g_log_a = (float)log((double)0.71f);                      // CR f32
        }
        if (t < 128)
            g_pow[t] = (float)pow((double)0.71f, (double)(t - 64));   // CR f32
        for (int i = t; i < NBIN; i += 1024) sh_hist[i] = 0u;
        __syncthreads();

        long S;
        if (N >= 65536) {
            S = 65536;
            // 512 contiguous 128-float chunks spread over N; 4 chunks in flight
            int warp = t >> 5, lane = t & 31;
            long cstride = ((long)N / 512) & ~3L;
            for (int kk = 0; kk < 16; kk += 4) {
                float4 v[4];
                #pragma unroll
                for (int u = 0; u < 4; u++) {
                    int c = (kk + u) * 32 + warp;
                    v[u] = *(const float4*)(scores + (long)c * cstride + lane * 4);
                }
                #pragma unroll
                for (int u = 0; u < 4; u++) {
                    float f[4] = {v[u].x, v[u].y, v[u].z, v[u].w};
                    #pragma unroll
                    for (int e = 0; e < 4; e++) {
                        int b = (int)(f[e] * (float)NBIN);
                        if (b < 0) b = 0;
                        if (b > NBIN - 1) b = NBIN - 1;
                        atomicAdd(&sh_hist[b], 1u);
                    }
                }
            }
        } else {
            S = N;
            for (int i = t; i < N; i += 1024) {
                int b = (int)(scores[i] * (float)NBIN);
                if (b < 0) b = 0;
                if (b > NBIN - 1) b = NBIN - 1;
                atomicAdd(&sh_hist[b], 1u);
            }
        }
        __syncthreads();

        u32 tgt = (u32)(((u64)RTARGET * (u64)S) / (u64)(N > 0 ? N : 1));
        if (tgt < 1) tgt = 1;

        u32 b0 = (u32)t * 8u;
        u32 local = 0;
        #pragma unroll
        for (int j = 0; j < 8; j++) local += sh_hist[b0 + j];
        sh_scan[t] = local;
        __syncthreads();
        for (int d = 1; d < 1024; d <<= 1) {
            u32 v = (t + d < 1024) ? sh_scan[t + d] : 0u;
            __syncthreads();
            sh_scan[t] += v;
            __syncthreads();
        }
        u32 cum = (t < 1023) ? sh_scan[t + 1] : 0u;
        for (int b = 7; b >= 0; b--) {
            u32 c = sh_hist[b0 + b];
            if (c && cum < tgt && cum + c >= tgt)
                g_thresh = __float_as_uint((float)(b0 + b) / (float)NBIN);
            cum += c;
        }
    } else {
        int gt = (blockIdx.x - 1) * blockDim.x + threadIdx.x;
        int gs = (gridDim.x - 1) * blockDim.x;
        for (int i = gt; i < 4 * TSIZE; i += gs) {
            ((u64*)g_tabk)[i] = EMPTYK;
            ((u64*)g_tabv)[i] = 0ull;
        }
        for (int i = gt; i < FBIN; i += gs) g_hist2[i] = 0u;
    }
}

// ---------------------------------------------------------------------------
// K2: scan scores, write packed (score_bits, ~idx) for candidates only.
// ---------------------------------------------------------------------------
__global__ __launch_bounds__(256) void scan_k(const float* __restrict__ scores, int N) {
    int t = blockIdx.x * blockDim.x + threadIdx.x;
    int lane = threadIdx.x & 31;
    long base = (long)t * 8;
    u32 T = g_thresh;

    u32 sb[8];
    u32 pmask = 0;
    if (base + 8 <= N) {
        const float4* s4 = (const float4*)(scores + base);
        float4 a = s4[0], b = s4[1];
        sb[0] = __float_as_uint(a.x); sb[1] = __float_as_uint(a.y);
        sb[2] = __float_as_uint(a.z); sb[3] = __float_as_uint(a.w);
        sb[4] = __float_as_uint(b.x); sb[5] = __float_as_uint(b.y);
        sb[6] = __float_as_uint(b.z); sb[7] = __float_as_uint(b.w);
        #pragma unroll
        for (int j = 0; j < 8; j++) if (sb[j] >= T) pmask |= (1u << j);
    } else if (base < N) {
        #pragma unroll
        for (int j = 0; j < 8; j++) {
            if (base + j < N) {
                sb[j] = __float_as_uint(scores[base + j]);
                if (sb[j] >= T) pmask |= (1u << j);
            }
        }
    }
    u32 cnt = __popc(pmask);

    u32 inc = cnt;
    #pragma unroll
    for (int d = 1; d < 32; d <<= 1) {
        u32 v = __shfl_up_sync(FULLM, inc, d);
        if (lane >= d) inc += v;
    }
    u32 wtot = __shfl_sync(FULLM, inc, 31);
    u32 wbase = 0;
    if (lane == 31 && wtot) wbase = atomicAdd(&g_ccnt, wtot);
    wbase = __shfl_sync(FULLM, wbase, 31);
    u32 p = wbase + inc - cnt;

    while (pmask) {
        int j = __ffs(pmask) - 1;
        pmask &= pmask - 1;
        if (p < CMAX)
            g_cval[p] = ((u64)sb[j] << 32) | (u64)(0xFFFFFFFFu - (u32)(base + j));
        p++;
    }
}

// ---------------------------------------------------------------------------
// K3: insert + resolve fused. 32 co-resident CTAs x 256. Each thread inserts
// its candidate (slots stay in registers), spin barrier (acq_rel ticket +
// acquire poll), then resolves from registers; keepers compact + bin hist.
// ---------------------------------------------------------------------------
__global__ __launch_bounds__(256) void insert_resolve_k(const float4* __restrict__ rects) {
    int tid = threadIdx.x;
    int lane = tid & 31;
    u32 cc = g_ccnt; if (cc > CMAX) cc = CMAX;
    const int num = g_num;
    u32 T = g_thresh;
    float Tf = __uint_as_float(T);
    float inv = (Tf < 0.999999f) ? ((float)FBIN / (1.0f - Tf)) : 0.0f;

    u32 i = blockIdx.x * blockDim.x + tid;
    u64 val = 0ull;
    u32 sl[4] = {0u, 0u, 0u, 0u};
    bool active = (i < cc);

    if (active) {
        val = g_cval[i];
        u32 gi = 0xFFFFFFFFu - (u32)(val & 0xFFFFFFFFull);
        float4 r = rects[gi];
        const float cx = r.x, cy = r.y, w = r.z, h = r.w;
        const float log_a = g_log_a;
        const float STEPF = (float)(1.0 / 0.71 - 1.0);

        float rw = logf(w) / log_a, rh = logf(h) / log_a;
        bool risky = false;
        #pragma unroll
        for (int m = 0; m < 4; m++) {
            if (m >= num) break;
            float off = (float)((double)m / (double)num);
            float fw = rw + off, fh = rh + off;
            float aw = fw - floorf(fw), ah = fh - floorf(fh);
            risky |= (aw < 1e-5f) | (aw > 1.0f - 1e-5f) | (ah < 1e-5f) | (ah > 1.0f - 1e-5f);
        }
        if (risky) {
            rw = (float)log((double)w) / log_a;
            rh = (float)log((double)h) / log_a;
        }

        for (int m = 0; m < num; m++) {
            float off = (float)((double)m / (double)num);
            int qw = (int)floorf(rw + off);
            int qh = (int)floorf(rh + off);
            int iw = qw + 64; iw = iw < 0 ? 0 : (iw > 127 ? 127 : iw);
            int ih = qh + 64; ih = ih < 0 ? 0 : (ih > 127 ? 127 : ih);
            float denw = STEPF * g_pow[iw];
            float denh = STEPF * g_pow[ih];
            int qx = (int)floorf(cx / denw + off);
            int qy = (int)floorf(cy / denh + off);
            u32 kh = (u32)((qw + 64) * 128 + (qh + 64));
            u32 kl = (u32)qx * 65536u + (u32)qy;
            u64 key = ((u64)kh << 32) | (u64)kl;

            u32 slot = (u32)mix64(key) & TMASK;
            for (;;) {
                u64 k = g_tabk[m][slot];
                if (k == key) break;
                if (k == EMPTYK) {
                    u64 old = atomicCAS(&g_tabk[m][slot], EMPTYK, key);
                    if (old == EMPTYK || old == key) break;
                }
                slot = (slot + 1) & TMASK;
            }
            atomicMax(&g_tabv[m][slot], val);
            sl[m] = slot;
        }
    }

    // ---- spin barrier across 32 co-resident CTAs ----
    __syncthreads();
    if (tid == 0) {
        atom_add_acq_rel(&g_tick);
        while (ld_acquire(&g_tick) < (u32)gridDim.x) { }
    }
    __syncthreads();

    // ---- resolve from registers; atomics bypassed L1 so __ldcg is coherent
    bool ok = false;
    if (active) {
        u64 tv[4];
        #pragma unroll
        for (int m = 0; m < 4; m++)
            tv[m] = (m < num) ? __ldcg(&g_tabv[m][sl[m]]) : val;
        ok = (tv[0] == val) & (tv[1] == val) & (tv[2] == val) & (tv[3] == val);
    }

    u32 mask = __ballot_sync(FULLM, ok);
    u32 wtot = __popc(mask);
    u32 wbase = 0;
    int leader = __ffs(mask) - 1;
    if (wtot && lane == leader) wbase = atomicAdd(&g_kcnt, wtot);
    if (wtot) wbase = __shfl_sync(FULLM, wbase, leader);
    if (ok) {
        u32 p = wbase + __popc(mask & ((1u << lane) - 1u));
        if (p < KMAX) g_kval[p] = val;
        float sf = __uint_as_float((u32)(val >> 32));
        int rel = (int)((sf - Tf) * inv);
        if (rel < 0) rel = 0;
        if (rel > FBIN - 1) rel = FBIN - 1;
        atomicAdd(&g_hist2[rel], 1u);
    }
}

// ---------------------------------------------------------------------------
// K4: single block: suffix-scan keeper bins -> rank bases; bucket-rank each
// selected keeper; exact order within tiny same-bin groups; write rows.
// ---------------------------------------------------------------------------
__global__ __launch_bounds__(1024) void finale_k(const float4* __restrict__ rects,
                                                 int maxp, float* __restrict__ out) {
    __shared__ u32 s_suf[FBIN];            // 16KB: suffix counts -> claim ctr
    __shared__ u32 s_scan[1024];           // 4KB
    __shared__ u64 s_key[SELCAP];          // 16KB
    __shared__ u16 s_bin[SELCAP];          // 4KB
    __shared__ u32 s_bsel, s_ksel;

    int t = threadIdx.x;
    u32 kcnt = g_kcnt; if (kcnt > KMAX) kcnt = KMAX;
    u32 T = g_thresh;
    float Tf = __uint_as_float(T);
    float inv = (Tf < 0.999999f) ? ((float)FBIN / (1.0f - Tf)) : 0.0f;

    if (t == 0) {
        s_bsel = 0;
        s_ksel = (kcnt < (u32)SELCAP) ? kcnt : (u32)SELCAP;
    }

    u32 b0 = (u32)t * 4u;
    uint4 cv = __ldcg((const uint4*)&g_hist2[b0]);
    u32 c0 = cv.x, c1 = cv.y, c2 = cv.z, c3 = cv.w;
    s_scan[t] = c0 + c1 + c2 + c3;
    __syncthreads();
    for (int d = 1; d < 1024; d <<= 1) {
        u32 v = (t + d < 1024) ? s_scan[t + d] : 0u;
        __syncthreads();
        s_scan[t] += v;
        __syncthreads();
    }
    u32 cum = (t < 1023) ? s_scan[t + 1] : 0u;   // keepers in chunks above
    s_suf[b0 + 3] = cum;
    s_suf[b0 + 2] = cum + c3;
    s_suf[b0 + 1] = cum + c3 + c2;
    s_suf[b0 + 0] = cum + c3 + c2 + c1;
    {
        u32 cc2 = cum;
        u32 cs[4] = {c0, c1, c2, c3};
        for (int b = 3; b >= 0; b--) {
            u32 c = cs[b];
            if (c && cc2 < (u32)maxp && cc2 + c >= (u32)maxp) {
                s_bsel = b0 + (u32)b;
                s_ksel = cc2 + c;
            }
            cc2 += c;
        }
    }
    __syncthreads();
    u32 bsel = s_bsel;
    u32 ksel = s_ksel; if (ksel > (u32)SELCAP) ksel = (u32)SELCAP;

    for (u32 i = t; i < kcnt; i += 1024) {
        u64 v = g_kval[i];
        float sf = __uint_as_float((u32)(v >> 32));
        int rel = (int)((sf - Tf) * inv);
        if (rel < 0) rel = 0;
        if (rel > FBIN - 1) rel = FBIN - 1;
        if ((u32)rel >= bsel) {
            u32 slot = atomicAdd(&s_suf[rel], 1u);
            if (slot < (u32)SELCAP) {
                s_key[slot] = v;
                s_bin[slot] = (u16)rel;
            }
        }
    }
    __syncthreads();

    for (u32 s = t; s < ksel; s += 1024) {
        u16 b = s_bin[s];
        u64 mykey = s_key[s];
        u32 g0 = s;
        while (g0 > 0 && s_bin[g0 - 1] == b) g0--;
        u32 g1 = s;
        while (g1 + 1 < ksel && s_bin[g1 + 1] == b) g1++;
        u32 rank = g0;
        for (u32 j = g0; j <= g1; j++) rank += (s_key[j] > mykey) ? 1u : 0u;
        if (rank < (u32)maxp) {
            u32 idx = 0xFFFFFFFFu - (u32)(mykey & 0xFFFFFFFFull);
            float4 bb = rects[idx];
            out[rank * 5 + 0] = bb.x;
            out[rank * 5 + 1] = bb.y;
            out[rank * 5 + 2] = bb.z;
            out[rank * 5 + 3] = bb.w;
            out[rank * 5 + 4] = __uint_as_float((u32)(mykey >> 32));
        }
    }
    u32 start = (ksel < (u32)maxp) ? ksel : (u32)maxp;
    for (u32 r = start + t; r < (u32)maxp; r += 1024) {
        out[r * 5 + 0] = 0.f;
        out[r * 5 + 1] = 0.f;
        out[r * 5 + 2] = 0.f;
        out[r * 5 + 3] = 0.f;
        out[r * 5 + 4] = 0.f;
    }
}

// ---------------------------------------------------------------------------
extern "C" void kernel_launch(void* const* d_in, const int* in_sizes, int n_in,
                              void* d_out, int out_size) {
    const float* rects  = (const float*)d_in[0];
    const float* scores = (const float*)d_in[1];
    const int*   nump   = (n_in > 2) ? (const int*)d_in[2] : nullptr;
    int N = in_sizes[0] / 4;
    int maxp = out_size / 5;
    if (maxp > 1024) maxp = 1024;
    float* out = (float*)d_out;

    int nbs = (int)(((long)N + 2047) / 2048);   // K2: 8 elems/thread, 256 thr

    init_sample_k  <<<64, 1024>>>(scores, nump, N);
    scan_k         <<<nbs, 256>>>(scores, N);
    insert_resolve_k<<<IRBLK, 256>>>((const float4*)rects);
    finale_k       <<<1, 1024>>>((const float4*)rects, maxp, out);
}